// round 15
// baseline (speedup 1.0000x reference)
#include <cuda_runtime.h>
#include <cuda_bf16.h>
#include <cuda_fp16.h>
#include <math.h>
#include <cstdint>

#define B_     16
#define L_     784
#define D_     384
#define H_     8
#define QK_    32
#define VD_    128
#define EH_    192          // per-head qkv width
#define QKVN_  1536
#define RESI_  625

#define FQT 112             // q rows per CTA (784 = 7*112)
#define FCK 112             // keys per chunk
#define VSTR 136            // V smem stride in fp16 (conflict-free trans ldsm)
#define KSTR 40             // K/Q smem stride in fp16
#define AON  (H_ * VD_)     // 1024
#define GS   40             // GEMM smem stride

// ---------------- scratch (static device globals; no runtime alloc) --------
__device__ __half        g_qkvf[(size_t)B_ * L_ * QKVN_];   // fp16 qkv for flash
__device__ __half        g_aof[(size_t)B_ * L_ * AON];      // fp16 attention out
__device__ __nv_bfloat16 g_biasbf[(size_t)H_ * L_ * L_];    // bias * log2(e)
__device__ __half        g_xf[(size_t)B_ * L_ * D_];
__device__ __half        g_wqf[QKVN_ * D_];
__device__ __half        g_wph[D_ * AON];                   // Wproj hi (fp16)
__device__ __half        g_wpl[D_ * AON];                   // Wproj lo (fp16 residual)

__device__ __forceinline__ uint32_t smem_u32(const void* p) {
    uint32_t a;
    asm("{ .reg .u64 t; cvta.to.shared.u64 t, %1; cvt.u32.u64 %0, t; }" : "=r"(a) : "l"(p));
    return a;
}
__device__ __forceinline__ void cpa16(uint32_t s, const void* g) {
    asm volatile("cp.async.cg.shared.global [%0], [%1], 16;" :: "r"(s), "l"(g));
}
__device__ __forceinline__ void cpa_commit() {
    asm volatile("cp.async.commit_group;" ::: "memory");
}
template <int N> __device__ __forceinline__ void cpa_wait() {
    asm volatile("cp.async.wait_group %0;" :: "n"(N) : "memory");
}

// ---------------- inline bicubic weights (RESI_/L_ resample) ---------------
__device__ __forceinline__ void interp4(int o, float* w, int* id) {
    const float a = -0.75f;
    float scale = (float)RESI_ / (float)L_;
    float src = ((float)o + 0.5f) * scale - 0.5f;
    float f = floorf(src);
    float t = src - f;
    float xs[4] = { t + 1.0f, t, 1.0f - t, 2.0f - t };
#pragma unroll
    for (int i = 0; i < 4; i++) {
        float ax = fabsf(xs[i]);
        float w1 = ((a + 2.0f) * ax - (a + 3.0f)) * ax * ax + 1.0f;
        float w2 = a * (((ax - 5.0f) * ax + 8.0f) * ax - 4.0f);
        w[i] = (ax <= 1.0f) ? w1 : ((ax < 2.0f) ? w2 : 0.0f);
        int v = (int)f - 1 + i;
        id[i] = v < 0 ? 0 : (v > RESI_ - 1 ? RESI_ - 1 : v);
    }
}

// ---------------- K1: fully fused bias build (scaled by log2e) --------------
__global__ __launch_bounds__(256) void bias_fused_kernel(
    const float* __restrict__ ab_table, const int* __restrict__ bias_idxs) {
    __shared__ float tr[RESI_];
    const float LOG2E = 1.4426950408889634f;
    int o = blockIdx.x, h = blockIdx.y;
    float wo[4]; int io[4];
    interp4(o, wo, io);
    const float* __restrict__ tab = ab_table + (size_t)h * RESI_;
    for (int j = threadIdx.x; j < RESI_; j += 256) {
        float s = 0.f;
#pragma unroll
        for (int a = 0; a < 4; a++) {
            int idx = __ldg(bias_idxs + (size_t)io[a] * RESI_ + j);
            s = fmaf(wo[a], __ldg(tab + idx), s);
        }
        tr[j] = s;
    }
    __syncthreads();
    __nv_bfloat16* dst = g_biasbf + ((size_t)h * L_ + o) * L_;
    for (int p = threadIdx.x; p < L_; p += 256) {
        float wp[4]; int ip[4];
        interp4(p, wp, ip);
        float s = 0.f;
#pragma unroll
        for (int bb = 0; bb < 4; bb++)
            s = fmaf(wp[bb], tr[ip[bb]], s);
        dst[p] = __float2bfloat16(s * LOG2E);
    }
}

// ---------------- K2: prep: x,Wqkv -> fp16; Wproj -> fp16 hi+lo ------------
__global__ void prep_kernel(
    const float* __restrict__ s0, __half* __restrict__ d0, int n0,
    const float* __restrict__ s1, __half* __restrict__ d1, int n1,
    const float* __restrict__ s2, __half* __restrict__ h2,
    __half* __restrict__ l2p, int n2)
{
    int i = blockIdx.x * blockDim.x + threadIdx.x;
    if (i < n0 + n1) {
        const float* src = (i < n0) ? s0 : s1;
        __half* dst = (i < n0) ? d0 : d1;
        if (i >= n0) i -= n0;
        float4 v = *(const float4*)(src + (size_t)i * 4);
        __half2 a = __floats2half2_rn(v.x, v.y);
        __half2 b = __floats2half2_rn(v.z, v.w);
        *(uint2*)(dst + (size_t)i * 4) = make_uint2(*(uint32_t*)&a, *(uint32_t*)&b);
    } else if (i < n0 + n1 + n2) {
        i -= n0 + n1;
        float4 v = *(const float4*)(s2 + (size_t)i * 4);
        __half2 h01 = __floats2half2_rn(v.x, v.y);
        __half2 h23 = __floats2half2_rn(v.z, v.w);
        float l0 = v.x - __half2float(h01.x), l1 = v.y - __half2float(h01.y);
        float l2 = v.z - __half2float(h23.x), l3 = v.w - __half2float(h23.y);
        __half2 q01 = __floats2half2_rn(l0, l1);
        __half2 q23 = __floats2half2_rn(l2, l3);
        *(uint2*)(h2 + (size_t)i * 4) = make_uint2(*(uint32_t*)&h01, *(uint32_t*)&h23);
        *(uint2*)(l2p + (size_t)i * 4) = make_uint2(*(uint32_t*)&q01, *(uint32_t*)&q23);
    }
}

// ---------------- mma.sync helpers -----------------------------------------
__device__ __forceinline__ void ldsm4(uint32_t& r0, uint32_t& r1, uint32_t& r2, uint32_t& r3,
                                      uint32_t addr) {
    asm volatile("ldmatrix.sync.aligned.m8n8.x4.shared.b16 {%0,%1,%2,%3}, [%4];"
                 : "=r"(r0), "=r"(r1), "=r"(r2), "=r"(r3) : "r"(addr));
}
__device__ __forceinline__ void ldsm4t(uint32_t& r0, uint32_t& r1, uint32_t& r2, uint32_t& r3,
                                       uint32_t addr) {
    asm volatile("ldmatrix.sync.aligned.m8n8.x4.trans.shared.b16 {%0,%1,%2,%3}, [%4];"
                 : "=r"(r0), "=r"(r1), "=r"(r2), "=r"(r3) : "r"(addr));
}
__device__ __forceinline__ void mma16816h(float* d, const uint32_t* a, const uint32_t* b) {
    asm volatile("mma.sync.aligned.m16n8k16.row.col.f32.f16.f16.f32 "
                 "{%0,%1,%2,%3}, {%4,%5,%6,%7}, {%8,%9}, {%0,%1,%2,%3};"
                 : "+f"(d[0]), "+f"(d[1]), "+f"(d[2]), "+f"(d[3])
                 : "r"(a[0]), "r"(a[1]), "r"(a[2]), "r"(a[3]), "r"(b[0]), "r"(b[1]));
}

// ---------------- K3: QKV GEMM, fp16 single-MMA -----------------------------
__global__ __launch_bounds__(256) void gemm_qkv_f16(
    const __half* __restrict__ Ag, const __half* __restrict__ Wg,
    __half* __restrict__ C, int M, int N, int K)
{
    extern __shared__ __align__(16) __half smh[];
    const int TS = 128 * GS;

    const int tid = threadIdx.x;
    const int wid = tid >> 5;
    const int lane = tid & 31;
    const int wm = wid >> 2;
    const int wn = wid & 3;
    const int bm = blockIdx.y * 128;
    const int bn = blockIdx.x * 128;
    const int q = lane >> 3;
    const int rr = lane & 7;

    float acc[4][4][4];
#pragma unroll
    for (int i = 0; i < 4; i++)
#pragma unroll
        for (int j = 0; j < 4; j++)
#pragma unroll
            for (int e = 0; e < 4; e++) acc[i][j][e] = 0.f;

    const int nch = K >> 5;

    auto prefetch = [&](int chunk, int stage) {
        int k0 = chunk << 5;
        __half* T = smh + stage * 2 * TS;
        const __half* gA = Ag + (size_t)bm * K + k0;
        const __half* gW = Wg + (size_t)bn * K + k0;
#pragma unroll
        for (int i = tid; i < 512; i += 256) {
            int row = i >> 2, seg = (i & 3) << 3;
            cpa16(smem_u32(T + row * GS + seg), gA + (size_t)row * K + seg);
            cpa16(smem_u32(T + TS + row * GS + seg), gW + (size_t)row * K + seg);
        }
    };

    prefetch(0, 0); cpa_commit();
    prefetch(1, 1); cpa_commit();

    for (int i = 0; i < nch; i++) {
        if (i < nch - 1) cpa_wait<1>(); else cpa_wait<0>();
        __syncthreads();
        const __half* TA = smh + (i & 1) * 2 * TS;
        const __half* TB = TA + TS;

#pragma unroll
        for (int ks = 0; ks < 2; ks++) {
            int kc = ks * 16;
            uint32_t ah[4][4];
#pragma unroll
            for (int ii2 = 0; ii2 < 4; ii2++) {
                int arow = wm * 64 + ii2 * 16 + (q & 1) * 8 + rr;
                int acol = kc + (q >> 1) * 8;
                ldsm4(ah[ii2][0], ah[ii2][1], ah[ii2][2], ah[ii2][3],
                      smem_u32(TA + arow * GS + acol));
            }
            uint32_t bh[4][2];
#pragma unroll
            for (int jp = 0; jp < 2; jp++) {
                int brow = wn * 32 + (jp * 2 + (q >> 1)) * 8 + rr;
                int bcol = kc + (q & 1) * 8;
                ldsm4(bh[jp * 2][0], bh[jp * 2][1], bh[jp * 2 + 1][0], bh[jp * 2 + 1][1],
                      smem_u32(TB + brow * GS + bcol));
            }
#pragma unroll
            for (int ii2 = 0; ii2 < 4; ii2++)
#pragma unroll
                for (int j = 0; j < 4; j++)
                    mma16816h(acc[ii2][j], ah[ii2], bh[j]);
        }
        __syncthreads();
        if (i + 2 < nch) { prefetch(i + 2, i & 1); cpa_commit(); }
    }

    const int gid = lane >> 2;
    const int tig = lane & 3;
#pragma unroll
    for (int i = 0; i < 4; i++) {
#pragma unroll
        for (int j = 0; j < 4; j++) {
            int row0 = bm + wm * 64 + i * 16 + gid;
            int col = bn + wn * 32 + j * 8 + tig * 2;
#pragma unroll
            for (int u = 0; u < 2; u++) {
                __half2 hh = __floats2half2_rn(acc[i][j][u * 2 + 0], acc[i][j][u * 2 + 1]);
                *(uint32_t*)(C + (size_t)(row0 + u * 8) * N + col) = *(uint32_t*)&hh;
            }
        }
    }
}

// ---------------- K5: proj GEMM: A fp16 single x (Wh + Wl) fp16 ------------
__global__ __launch_bounds__(256) void gemm_proj_f16(
    const __half* __restrict__ Ag,
    const __half* __restrict__ Whg, const __half* __restrict__ Wlg,
    const float* __restrict__ bias, float* __restrict__ Cf,
    int M, int N, int K)
{
    extern __shared__ __align__(16) __half smh[];
    const int TS = 128 * GS;

    const int tid = threadIdx.x;
    const int wid = tid >> 5;
    const int lane = tid & 31;
    const int wm = wid >> 2;
    const int wn = wid & 3;
    const int bm = blockIdx.y * 128;
    const int bn = blockIdx.x * 128;
    const int q = lane >> 3;
    const int rr = lane & 7;

    float acc[4][4][4];
#pragma unroll
    for (int i = 0; i < 4; i++)
#pragma unroll
        for (int j = 0; j < 4; j++)
#pragma unroll
            for (int e = 0; e < 4; e++) acc[i][j][e] = 0.f;

    const int nch = K >> 5;

    auto prefetch = [&](int chunk, int stage) {
        int k0 = chunk << 5;
        __half* T = smh + stage * 3 * TS;
        const __half* gA = Ag + (size_t)bm * K + k0;
        const __half* gH = Whg + (size_t)bn * K + k0;
        const __half* gL = Wlg + (size_t)bn * K + k0;
#pragma unroll
        for (int i = tid; i < 512; i += 256) {
            int row = i >> 2, seg = (i & 3) << 3;
            cpa16(smem_u32(T + row * GS + seg), gA + (size_t)row * K + seg);
            cpa16(smem_u32(T + TS + row * GS + seg), gH + (size_t)row * K + seg);
            cpa16(smem_u32(T + 2 * TS + row * GS + seg), gL + (size_t)row * K + seg);
        }
    };

    prefetch(0, 0); cpa_commit();
    prefetch(1, 1); cpa_commit();

    for (int i = 0; i < nch; i++) {
        if (i < nch - 1) cpa_wait<1>(); else cpa_wait<0>();
        __syncthreads();
        const __half* TA = smh + (i & 1) * 3 * TS;
        const __half* TH = TA + TS;
        const __half* TL = TA + 2 * TS;

#pragma unroll
        for (int ks = 0; ks < 2; ks++) {
            int kc = ks * 16;
            uint32_t ah[4][4];
#pragma unroll
            for (int ii2 = 0; ii2 < 4; ii2++) {
                int arow = wm * 64 + ii2 * 16 + (q & 1) * 8 + rr;
                int acol = kc + (q >> 1) * 8;
                ldsm4(ah[ii2][0], ah[ii2][1], ah[ii2][2], ah[ii2][3],
                      smem_u32(TA + arow * GS + acol));
            }
            uint32_t bh[4][2], bl[4][2];
#pragma unroll
            for (int jp = 0; jp < 2; jp++) {
                int brow = wn * 32 + (jp * 2 + (q >> 1)) * 8 + rr;
                int bcol = kc + (q & 1) * 8;
                ldsm4(bh[jp * 2][0], bh[jp * 2][1], bh[jp * 2 + 1][0], bh[jp * 2 + 1][1],
                      smem_u32(TH + brow * GS + bcol));
                ldsm4(bl[jp * 2][0], bl[jp * 2][1], bl[jp * 2 + 1][0], bl[jp * 2 + 1][1],
                      smem_u32(TL + brow * GS + bcol));
            }
#pragma unroll
            for (int ii2 = 0; ii2 < 4; ii2++)
#pragma unroll
                for (int j = 0; j < 4; j++) {
                    mma16816h(acc[ii2][j], ah[ii2], bh[j]);
                    mma16816h(acc[ii2][j], ah[ii2], bl[j]);
                }
        }
        __syncthreads();
        if (i + 2 < nch) { prefetch(i + 2, i & 1); cpa_commit(); }
    }

    const int gid = lane >> 2;
    const int tig = lane & 3;
#pragma unroll
    for (int i = 0; i < 4; i++) {
#pragma unroll
        for (int j = 0; j < 4; j++) {
            int row0 = bm + wm * 64 + i * 16 + gid;
            int col = bn + wn * 32 + j * 8 + tig * 2;
            float2 v0 = make_float2(acc[i][j][0] + bias[col], acc[i][j][1] + bias[col + 1]);
            float2 v1 = make_float2(acc[i][j][2] + bias[col], acc[i][j][3] + bias[col + 1]);
            *(float2*)(Cf + (size_t)row0 * N + col) = v0;
            *(float2*)(Cf + (size_t)(row0 + 8) * N + col) = v1;
        }
    }
}

// ---------------- K4: fp16 flash attention, double-buffered, 2 CTAs/SM ------
struct FlashKV {
    __half Kh[FQT][KSTR];
    __half Vh[FCK][VSTR];
};
struct FlashSmemAll {
    __half Qh[FQT][KSTR];
    FlashKV kv[2];
};

__global__ __launch_bounds__(224, 2) void flash_mma_kernel() {
    extern __shared__ __align__(16) char smraw[];
    FlashSmemAll& SM = *reinterpret_cast<FlashSmemAll*>(smraw);
    const int tid = threadIdx.x;
    const int warp = tid >> 5, lane = tid & 31;
    const int b = blockIdx.z, h = blockIdx.y, qb = blockIdx.x;
    const int q8 = lane >> 3, rr = lane & 7;
    const int gid = lane >> 2, tig = lane & 3;
    const float scale2 = 0.17677669529663687f * 1.4426950408889634f;

    auto pf_chunk = [&](int chunk, FlashKV* KV) {
        int j0 = chunk * FCK;
        const __half* Kg = g_qkvf + (size_t)(b * L_ + j0) * QKVN_ + h * EH_ + QK_;
#pragma unroll
        for (int i = tid; i < 448; i += 224) {
            int row = i >> 2, seg = (i & 3) << 3;
            cpa16(smem_u32(&KV->Kh[row][seg]), Kg + (size_t)row * QKVN_ + seg);
        }
        const __half* Vg = Kg + QK_;
#pragma unroll
        for (int i = tid; i < 1792; i += 224) {
            int row = i >> 4, seg = (i & 15) << 3;
            cpa16(smem_u32(&KV->Vh[row][seg]), Vg + (size_t)row * QKVN_ + seg);
        }
    };

    {
        const __half* Qg = g_qkvf + (size_t)(b * L_ + qb * FQT) * QKVN_ + h * EH_;
#pragma unroll
        for (int i = tid; i < 448; i += 224) {
            int row = i >> 2, seg = (i & 3) << 3;
            cpa16(smem_u32(&SM.Qh[row][seg]), Qg + (size_t)row * QKVN_ + seg);
        }
    }
    pf_chunk(0, &SM.kv[0]); cpa_commit();
    pf_chunk(1, &SM.kv[1]); cpa_commit();

    cpa_wait<1>();
    __syncthreads();

    uint32_t qhf[2][4];
#pragma unroll
    for (int s = 0; s < 2; s++) {
        int arow = warp * 16 + (q8 & 1) * 8 + rr;
        int acol = s * 16 + (q8 >> 1) * 8;
        ldsm4(qhf[s][0], qhf[s][1], qhf[s][2], qhf[s][3], smem_u32(&SM.Qh[arow][acol]));
    }

    float out[16][4];
#pragma unroll
    for (int j = 0; j < 16; j++)
#pragma unroll
        for (int e = 0; e < 4; e++) out[j][e] = 0.f;
    float m0 = -1e30f, m1 = -1e30f, l0s = 0.f, l1s = 0.f;

    const int r0 = qb * FQT + warp * 16 + gid;
    const __nv_bfloat16* biasbase = g_biasbf + ((size_t)h * L_ + r0) * L_;

    for (int kc = 0; kc < 7; kc++) {
        int j0 = kc * FCK;
        if (kc > 0) {
            if (kc < 6) cpa_wait<1>(); else cpa_wait<0>();
            __syncthreads();
        }
        FlashKV& KV = SM.kv[kc & 1];

        // ---- S = Q K^T (single fp16 MMA) ----
        float sa[14][4];
#pragma unroll
        for (int t = 0; t < 14; t++)
#pragma unroll
            for (int e = 0; e < 4; e++) sa[t][e] = 0.f;
#pragma unroll
        for (int s = 0; s < 2; s++) {
#pragma unroll
            for (int tp = 0; tp < 7; tp++) {
                uint32_t bh[4];
                int brow = (tp * 2 + (q8 >> 1)) * 8 + rr;
                int bcol = s * 16 + (q8 & 1) * 8;
                ldsm4(bh[0], bh[1], bh[2], bh[3], smem_u32(&KV.Kh[brow][bcol]));
                mma16816h(sa[tp * 2 + 0], qhf[s], bh + 0);
                mma16816h(sa[tp * 2 + 1], qhf[s], bh + 2);
            }
        }

        // ---- (bias + scale)*log2e + row max (log2 domain) ----
        float ml0 = -1e30f, ml1 = -1e30f;
#pragma unroll
        for (int t = 0; t < 14; t++) {
            int col = j0 + t * 8 + tig * 2;
            float2 b0 = __bfloat1622float2(*(const __nv_bfloat162*)(biasbase + col));
            float2 b1 = __bfloat1622float2(*(const __nv_bfloat162*)(biasbase + (size_t)8 * L_ + col));
            sa[t][0] = fmaf(sa[t][0], scale2, b0.x);
            sa[t][1] = fmaf(sa[t][1], scale2, b0.y);
            sa[t][2] = fmaf(sa[t][2], scale2, b1.x);
            sa[t][3] = fmaf(sa[t][3], scale2, b1.y);
            ml0 = fmaxf(ml0, fmaxf(sa[t][0], sa[t][1]));
            ml1 = fmaxf(ml1, fmaxf(sa[t][2], sa[t][3]));
        }
        ml0 = fmaxf(ml0, __shfl_xor_sync(0xffffffffu, ml0, 1));
        ml0 = fmaxf(ml0, __shfl_xor_sync(0xffffffffu, ml0, 2));
        ml1 = fmaxf(ml1, __shfl_xor_sync(0xffffffffu, ml1, 1));
        ml1 = fmaxf(ml1, __shfl_xor_sync(0xffffffffu, ml1, 2));
        float mn0 = fmaxf(m0, ml0), mn1 = fmaxf(m1, ml1);
        float c0 = exp2f(m0 - mn0), c1 = exp2f(m1 - mn1);
        m0 = mn0; m1 = mn1;
#pragma unroll
        for (int j = 0; j < 16; j++) {
            out[j][0] *= c0; out[j][1] *= c0;
            out[j][2] *= c1; out[j][3] *= c1;
        }

        // ---- fused exp2 + PV (single fp16 MMA per tile) ----
        float rs0 = 0.f, rs1 = 0.f;
#pragma unroll
        for (int s2 = 0; s2 < 7; s2++) {
            uint32_t pah[4];
#pragma unroll
            for (int u = 0; u < 2; u++) {
                int t = s2 * 2 + u;
                float p0 = exp2f(sa[t][0] - mn0);
                float p1 = exp2f(sa[t][1] - mn0);
                float p2 = exp2f(sa[t][2] - mn1);
                float p3 = exp2f(sa[t][3] - mn1);
                rs0 += p0 + p1; rs1 += p2 + p3;
                __half2 h01 = __floats2half2_rn(p0, p1);
                __half2 h23 = __floats2half2_rn(p2, p3);
                pah[u * 2 + 0] = *(uint32_t*)&h01;
                pah[u * 2 + 1] = *(uint32_t*)&h23;
            }
#pragma unroll
            for (int jp = 0; jp < 8; jp++) {
                uint32_t vh[4];
                int vrow = s2 * 16 + (lane & 15);
                int vcol = (jp * 2 + (lane >> 4)) * 8;
                ldsm4t(vh[0], vh[1], vh[2], vh[3], smem_u32(&KV.Vh[vrow][vcol]));
                mma16816h(out[jp * 2 + 0], pah, vh + 0);
                mma16816h(out[jp * 2 + 1], pah, vh + 2);
            }
        }
        rs0 += __shfl_xor_sync(0xffffffffu, rs0, 1);
        rs0 += __shfl_xor_sync(0xffffffffu, rs0, 2);
        rs1 += __shfl_xor_sync(0xffffffffu, rs1, 1);
        rs1 += __shfl_xor_sync(0xffffffffu, rs1, 2);
        l0s = l0s * c0 + rs0;
        l1s = l1s * c1 + rs1;

        __syncthreads();
        if (kc + 2 <= 6) { pf_chunk(kc + 2, &SM.kv[kc & 1]); cpa_commit(); }
    }

    // ---- epilogue: normalize + fp16 write for proj GEMM ----
    float inv0 = 1.0f / l0s, inv1 = 1.0f / l1s;
    __half* of = g_aof + (size_t)(b * L_ + r0) * AON + h * VD_;
#pragma unroll
    for (int j = 0; j < 16; j++) {
        int col = j * 8 + tig * 2;
        {
            __half2 hh = __floats2half2_rn(out[j][0] * inv0, out[j][1] * inv0);
            *(uint32_t*)(of + col) = *(uint32_t*)&hh;
        }
        {
            __half2 hh = __floats2half2_rn(out[j][2] * inv1, out[j][3] * inv1);
            *(uint32_t*)(of + (size_t)8 * AON + col) = *(uint32_t*)&hh;
        }
    }
}

// ---------------- launch ---------------------------------------------------
extern "C" void kernel_launch(void* const* d_in, const int* in_sizes, int n_in,
                              void* d_out, int out_size) {
    const float* x         = (const float*)d_in[0];
    const float* Wqkv      = (const float*)d_in[1];
    const float* Wproj     = (const float*)d_in[2];
    const float* bproj     = (const float*)d_in[3];
    const float* ab_table  = (const float*)d_in[4];
    const int*   bias_idxs = (const int*)d_in[5];
    float* out = (float*)d_out;

    __half *pqkvf, *pxf, *pwqf, *paof, *pwph, *pwpl;
    cudaGetSymbolAddress((void**)&pxf, g_xf);
    cudaGetSymbolAddress((void**)&pwqf, g_wqf);
    cudaGetSymbolAddress((void**)&pwph, g_wph);
    cudaGetSymbolAddress((void**)&pwpl, g_wpl);
    cudaGetSymbolAddress((void**)&pqkvf, g_qkvf);
    cudaGetSymbolAddress((void**)&paof, g_aof);

    const int FSM = (int)sizeof(FlashSmemAll);   // 87808
    cudaFuncSetAttribute(flash_mma_kernel, cudaFuncAttributeMaxDynamicSharedMemorySize, FSM);
    const int GSMQ = 2 * 2 * 128 * GS * (int)sizeof(__half);   // 40960
    const int GSMP = 2 * 3 * 128 * GS * (int)sizeof(__half);   // 61440
    cudaFuncSetAttribute(gemm_qkv_f16, cudaFuncAttributeMaxDynamicSharedMemorySize, GSMQ);
    cudaFuncSetAttribute(gemm_proj_f16, cudaFuncAttributeMaxDynamicSharedMemorySize, GSMP);

    dim3 gbias(L_, H_);
    bias_fused_kernel<<<gbias, 256>>>(ab_table, bias_idxs);

    {
        int n0 = (B_ * L_ * D_) / 4;
        int n1 = (QKVN_ * D_) / 4;
        int n2 = (D_ * AON) / 4;
        int tot = n0 + n1 + n2;
        prep_kernel<<<(tot + 255) / 256, 256>>>(x, pxf, n0, Wqkv, pwqf, n1,
                                                Wproj, pwph, pwpl, n2);
    }

    dim3 gqkv(QKVN_ / 128, (B_ * L_) / 128);
    gemm_qkv_f16<<<gqkv, 256, GSMQ>>>(pxf, pwqf, pqkvf, B_ * L_, QKVN_, D_);

    dim3 gatt(L_ / FQT, H_, B_);
    flash_mma_kernel<<<gatt, 224, FSM>>>();

    dim3 gproj(D_ / 128, (B_ * L_) / 128);
    gemm_proj_f16<<<gproj, 256, GSMP>>>(paof, pwph, pwpl, bproj,
                                        out, B_ * L_, D_, AON);
}

// round 16
// speedup vs baseline: 1.5237x; 1.5237x over previous
#include <cuda_runtime.h>
#include <cuda_bf16.h>
#include <cuda_fp16.h>
#include <math.h>
#include <cstdint>

#define B_     16
#define L_     784
#define D_     384
#define H_     8
#define QK_    32
#define VD_    128
#define EH_    192          // per-head qkv width
#define QKVN_  1536
#define RESI_  625

#define FQT 112             // q rows per CTA (784 = 7*112)
#define FCK 112             // keys per chunk
#define VSTR 136            // V smem stride in fp16 (conflict-free trans ldsm)
#define KSTR 40             // K/Q smem stride in fp16
#define AON  (H_ * VD_)     // 1024
#define GS   40             // GEMM smem stride

// ---------------- scratch (static device globals; no runtime alloc) --------
__device__ __half        g_qkvf[(size_t)B_ * L_ * QKVN_];   // fp16 qkv for flash
__device__ __half        g_aof[(size_t)B_ * L_ * AON];      // fp16 attention out
__device__ __nv_bfloat16 g_biasbf[(size_t)H_ * L_ * L_];    // bias * log2(e)
__device__ __half        g_xf[(size_t)B_ * L_ * D_];
__device__ __half        g_wqf[QKVN_ * D_];
__device__ __half        g_wph[D_ * AON];                   // Wproj hi (fp16)
__device__ __half        g_wpl[D_ * AON];                   // Wproj lo (fp16 residual)

__device__ __forceinline__ uint32_t smem_u32(const void* p) {
    uint32_t a;
    asm("{ .reg .u64 t; cvta.to.shared.u64 t, %1; cvt.u32.u64 %0, t; }" : "=r"(a) : "l"(p));
    return a;
}
__device__ __forceinline__ void cpa16(uint32_t s, const void* g) {
    asm volatile("cp.async.cg.shared.global [%0], [%1], 16;" :: "r"(s), "l"(g));
}
__device__ __forceinline__ void cpa_commit() {
    asm volatile("cp.async.commit_group;" ::: "memory");
}
template <int N> __device__ __forceinline__ void cpa_wait() {
    asm volatile("cp.async.wait_group %0;" :: "n"(N) : "memory");
}

// ---------------- inline bicubic weights (RESI_/L_ resample) ---------------
__device__ __forceinline__ void interp4(int o, float* w, int* id) {
    const float a = -0.75f;
    float scale = (float)RESI_ / (float)L_;
    float src = ((float)o + 0.5f) * scale - 0.5f;
    float f = floorf(src);
    float t = src - f;
    float xs[4] = { t + 1.0f, t, 1.0f - t, 2.0f - t };
#pragma unroll
    for (int i = 0; i < 4; i++) {
        float ax = fabsf(xs[i]);
        float w1 = ((a + 2.0f) * ax - (a + 3.0f)) * ax * ax + 1.0f;
        float w2 = a * (((ax - 5.0f) * ax + 8.0f) * ax - 4.0f);
        w[i] = (ax <= 1.0f) ? w1 : ((ax < 2.0f) ? w2 : 0.0f);
        int v = (int)f - 1 + i;
        id[i] = v < 0 ? 0 : (v > RESI_ - 1 ? RESI_ - 1 : v);
    }
}

// ---------------- K1: fully fused bias build (scaled by log2e) --------------
__global__ __launch_bounds__(256) void bias_fused_kernel(
    const float* __restrict__ ab_table, const int* __restrict__ bias_idxs) {
    __shared__ float tr[RESI_];
    const float LOG2E = 1.4426950408889634f;
    int o = blockIdx.x, h = blockIdx.y;
    float wo[4]; int io[4];
    interp4(o, wo, io);
    const float* __restrict__ tab = ab_table + (size_t)h * RESI_;
    for (int j = threadIdx.x; j < RESI_; j += 256) {
        float s = 0.f;
#pragma unroll
        for (int a = 0; a < 4; a++) {
            int idx = __ldg(bias_idxs + (size_t)io[a] * RESI_ + j);
            s = fmaf(wo[a], __ldg(tab + idx), s);
        }
        tr[j] = s;
    }
    __syncthreads();
    __nv_bfloat16* dst = g_biasbf + ((size_t)h * L_ + o) * L_;
    for (int p = threadIdx.x; p < L_; p += 256) {
        float wp[4]; int ip[4];
        interp4(p, wp, ip);
        float s = 0.f;
#pragma unroll
        for (int bb = 0; bb < 4; bb++)
            s = fmaf(wp[bb], tr[ip[bb]], s);
        dst[p] = __float2bfloat16(s * LOG2E);
    }
}

// ---------------- K2: prep: x,Wqkv -> fp16; Wproj -> fp16 hi+lo ------------
__global__ void prep_kernel(
    const float* __restrict__ s0, __half* __restrict__ d0, int n0,
    const float* __restrict__ s1, __half* __restrict__ d1, int n1,
    const float* __restrict__ s2, __half* __restrict__ h2,
    __half* __restrict__ l2p, int n2)
{
    int i = blockIdx.x * blockDim.x + threadIdx.x;
    if (i < n0 + n1) {
        const float* src = (i < n0) ? s0 : s1;
        __half* dst = (i < n0) ? d0 : d1;
        if (i >= n0) i -= n0;
        float4 v = *(const float4*)(src + (size_t)i * 4);
        __half2 a = __floats2half2_rn(v.x, v.y);
        __half2 b = __floats2half2_rn(v.z, v.w);
        *(uint2*)(dst + (size_t)i * 4) = make_uint2(*(uint32_t*)&a, *(uint32_t*)&b);
    } else if (i < n0 + n1 + n2) {
        i -= n0 + n1;
        float4 v = *(const float4*)(s2 + (size_t)i * 4);
        __half2 h01 = __floats2half2_rn(v.x, v.y);
        __half2 h23 = __floats2half2_rn(v.z, v.w);
        float l0 = v.x - __half2float(h01.x), l1 = v.y - __half2float(h01.y);
        float l2 = v.z - __half2float(h23.x), l3 = v.w - __half2float(h23.y);
        __half2 q01 = __floats2half2_rn(l0, l1);
        __half2 q23 = __floats2half2_rn(l2, l3);
        *(uint2*)(h2 + (size_t)i * 4) = make_uint2(*(uint32_t*)&h01, *(uint32_t*)&h23);
        *(uint2*)(l2p + (size_t)i * 4) = make_uint2(*(uint32_t*)&q01, *(uint32_t*)&q23);
    }
}

// ---------------- mma.sync helpers -----------------------------------------
__device__ __forceinline__ void ldsm4(uint32_t& r0, uint32_t& r1, uint32_t& r2, uint32_t& r3,
                                      uint32_t addr) {
    asm volatile("ldmatrix.sync.aligned.m8n8.x4.shared.b16 {%0,%1,%2,%3}, [%4];"
                 : "=r"(r0), "=r"(r1), "=r"(r2), "=r"(r3) : "r"(addr));
}
__device__ __forceinline__ void ldsm4t(uint32_t& r0, uint32_t& r1, uint32_t& r2, uint32_t& r3,
                                       uint32_t addr) {
    asm volatile("ldmatrix.sync.aligned.m8n8.x4.trans.shared.b16 {%0,%1,%2,%3}, [%4];"
                 : "=r"(r0), "=r"(r1), "=r"(r2), "=r"(r3) : "r"(addr));
}
__device__ __forceinline__ void mma16816h(float* d, const uint32_t* a, const uint32_t* b) {
    asm volatile("mma.sync.aligned.m16n8k16.row.col.f32.f16.f16.f32 "
                 "{%0,%1,%2,%3}, {%4,%5,%6,%7}, {%8,%9}, {%0,%1,%2,%3};"
                 : "+f"(d[0]), "+f"(d[1]), "+f"(d[2]), "+f"(d[3])
                 : "r"(a[0]), "r"(a[1]), "r"(a[2]), "r"(a[3]), "r"(b[0]), "r"(b[1]));
}

// ---------------- K3: QKV GEMM, fp16 single-MMA -----------------------------
__global__ __launch_bounds__(256) void gemm_qkv_f16(
    const __half* __restrict__ Ag, const __half* __restrict__ Wg,
    __half* __restrict__ C, int M, int N, int K)
{
    extern __shared__ __align__(16) __half smh[];
    const int TS = 128 * GS;

    const int tid = threadIdx.x;
    const int wid = tid >> 5;
    const int lane = tid & 31;
    const int wm = wid >> 2;
    const int wn = wid & 3;
    const int bm = blockIdx.y * 128;
    const int bn = blockIdx.x * 128;
    const int q = lane >> 3;
    const int rr = lane & 7;

    float acc[4][4][4];
#pragma unroll
    for (int i = 0; i < 4; i++)
#pragma unroll
        for (int j = 0; j < 4; j++)
#pragma unroll
            for (int e = 0; e < 4; e++) acc[i][j][e] = 0.f;

    const int nch = K >> 5;

    auto prefetch = [&](int chunk, int stage) {
        int k0 = chunk << 5;
        __half* T = smh + stage * 2 * TS;
        const __half* gA = Ag + (size_t)bm * K + k0;
        const __half* gW = Wg + (size_t)bn * K + k0;
#pragma unroll
        for (int i = tid; i < 512; i += 256) {
            int row = i >> 2, seg = (i & 3) << 3;
            cpa16(smem_u32(T + row * GS + seg), gA + (size_t)row * K + seg);
            cpa16(smem_u32(T + TS + row * GS + seg), gW + (size_t)row * K + seg);
        }
    };

    prefetch(0, 0); cpa_commit();
    prefetch(1, 1); cpa_commit();

    for (int i = 0; i < nch; i++) {
        if (i < nch - 1) cpa_wait<1>(); else cpa_wait<0>();
        __syncthreads();
        const __half* TA = smh + (i & 1) * 2 * TS;
        const __half* TB = TA + TS;

#pragma unroll
        for (int ks = 0; ks < 2; ks++) {
            int kc = ks * 16;
            uint32_t ah[4][4];
#pragma unroll
            for (int ii2 = 0; ii2 < 4; ii2++) {
                int arow = wm * 64 + ii2 * 16 + (q & 1) * 8 + rr;
                int acol = kc + (q >> 1) * 8;
                ldsm4(ah[ii2][0], ah[ii2][1], ah[ii2][2], ah[ii2][3],
                      smem_u32(TA + arow * GS + acol));
            }
            uint32_t bh[4][2];
#pragma unroll
            for (int jp = 0; jp < 2; jp++) {
                int brow = wn * 32 + (jp * 2 + (q >> 1)) * 8 + rr;
                int bcol = kc + (q & 1) * 8;
                ldsm4(bh[jp * 2][0], bh[jp * 2][1], bh[jp * 2 + 1][0], bh[jp * 2 + 1][1],
                      smem_u32(TB + brow * GS + bcol));
            }
#pragma unroll
            for (int ii2 = 0; ii2 < 4; ii2++)
#pragma unroll
                for (int j = 0; j < 4; j++)
                    mma16816h(acc[ii2][j], ah[ii2], bh[j]);
        }
        __syncthreads();
        if (i + 2 < nch) { prefetch(i + 2, i & 1); cpa_commit(); }
    }

    const int gid = lane >> 2;
    const int tig = lane & 3;
#pragma unroll
    for (int i = 0; i < 4; i++) {
#pragma unroll
        for (int j = 0; j < 4; j++) {
            int row0 = bm + wm * 64 + i * 16 + gid;
            int col = bn + wn * 32 + j * 8 + tig * 2;
#pragma unroll
            for (int u = 0; u < 2; u++) {
                __half2 hh = __floats2half2_rn(acc[i][j][u * 2 + 0], acc[i][j][u * 2 + 1]);
                *(uint32_t*)(C + (size_t)(row0 + u * 8) * N + col) = *(uint32_t*)&hh;
            }
        }
    }
}

// ---------------- K5: proj GEMM: A fp16 single x (Wh + Wl) fp16 ------------
__global__ __launch_bounds__(256) void gemm_proj_f16(
    const __half* __restrict__ Ag,
    const __half* __restrict__ Whg, const __half* __restrict__ Wlg,
    const float* __restrict__ bias, float* __restrict__ Cf,
    int M, int N, int K)
{
    extern __shared__ __align__(16) __half smh[];
    const int TS = 128 * GS;

    const int tid = threadIdx.x;
    const int wid = tid >> 5;
    const int lane = tid & 31;
    const int wm = wid >> 2;
    const int wn = wid & 3;
    const int bm = blockIdx.y * 128;
    const int bn = blockIdx.x * 128;
    const int q = lane >> 3;
    const int rr = lane & 7;

    float acc[4][4][4];
#pragma unroll
    for (int i = 0; i < 4; i++)
#pragma unroll
        for (int j = 0; j < 4; j++)
#pragma unroll
            for (int e = 0; e < 4; e++) acc[i][j][e] = 0.f;

    const int nch = K >> 5;

    auto prefetch = [&](int chunk, int stage) {
        int k0 = chunk << 5;
        __half* T = smh + stage * 3 * TS;
        const __half* gA = Ag + (size_t)bm * K + k0;
        const __half* gH = Whg + (size_t)bn * K + k0;
        const __half* gL = Wlg + (size_t)bn * K + k0;
#pragma unroll
        for (int i = tid; i < 512; i += 256) {
            int row = i >> 2, seg = (i & 3) << 3;
            cpa16(smem_u32(T + row * GS + seg), gA + (size_t)row * K + seg);
            cpa16(smem_u32(T + TS + row * GS + seg), gH + (size_t)row * K + seg);
            cpa16(smem_u32(T + 2 * TS + row * GS + seg), gL + (size_t)row * K + seg);
        }
    };

    prefetch(0, 0); cpa_commit();
    prefetch(1, 1); cpa_commit();

    for (int i = 0; i < nch; i++) {
        if (i < nch - 1) cpa_wait<1>(); else cpa_wait<0>();
        __syncthreads();
        const __half* TA = smh + (i & 1) * 3 * TS;
        const __half* TH = TA + TS;
        const __half* TL = TA + 2 * TS;

#pragma unroll
        for (int ks = 0; ks < 2; ks++) {
            int kc = ks * 16;
            uint32_t ah[4][4];
#pragma unroll
            for (int ii2 = 0; ii2 < 4; ii2++) {
                int arow = wm * 64 + ii2 * 16 + (q & 1) * 8 + rr;
                int acol = kc + (q >> 1) * 8;
                ldsm4(ah[ii2][0], ah[ii2][1], ah[ii2][2], ah[ii2][3],
                      smem_u32(TA + arow * GS + acol));
            }
            uint32_t bh[4][2], bl[4][2];
#pragma unroll
            for (int jp = 0; jp < 2; jp++) {
                int brow = wn * 32 + (jp * 2 + (q >> 1)) * 8 + rr;
                int bcol = kc + (q & 1) * 8;
                ldsm4(bh[jp * 2][0], bh[jp * 2][1], bh[jp * 2 + 1][0], bh[jp * 2 + 1][1],
                      smem_u32(TH + brow * GS + bcol));
                ldsm4(bl[jp * 2][0], bl[jp * 2][1], bl[jp * 2 + 1][0], bl[jp * 2 + 1][1],
                      smem_u32(TL + brow * GS + bcol));
            }
#pragma unroll
            for (int ii2 = 0; ii2 < 4; ii2++)
#pragma unroll
                for (int j = 0; j < 4; j++) {
                    mma16816h(acc[ii2][j], ah[ii2], bh[j]);
                    mma16816h(acc[ii2][j], ah[ii2], bl[j]);
                }
        }
        __syncthreads();
        if (i + 2 < nch) { prefetch(i + 2, i & 1); cpa_commit(); }
    }

    const int gid = lane >> 2;
    const int tig = lane & 3;
#pragma unroll
    for (int i = 0; i < 4; i++) {
#pragma unroll
        for (int j = 0; j < 4; j++) {
            int row0 = bm + wm * 64 + i * 16 + gid;
            int col = bn + wn * 32 + j * 8 + tig * 2;
            float2 v0 = make_float2(acc[i][j][0] + bias[col], acc[i][j][1] + bias[col + 1]);
            float2 v1 = make_float2(acc[i][j][2] + bias[col], acc[i][j][3] + bias[col + 1]);
            *(float2*)(Cf + (size_t)row0 * N + col) = v0;
            *(float2*)(Cf + (size_t)(row0 + 8) * N + col) = v1;
        }
    }
}

// ---------------- K4: fp16 flash attention, double-buffered, 2 CTAs/SM ------
struct FlashKV {
    __half Kh[FQT][KSTR];
    __half Vh[FCK][VSTR];
};
struct FlashSmemAll {
    __half Qh[FQT][KSTR];
    FlashKV kv[2];
};

__global__ __launch_bounds__(224, 2) void flash_mma_kernel() {
    extern __shared__ __align__(16) char smraw[];
    FlashSmemAll& SM = *reinterpret_cast<FlashSmemAll*>(smraw);
    const int tid = threadIdx.x;
    const int warp = tid >> 5, lane = tid & 31;
    const int b = blockIdx.z, h = blockIdx.y, qb = blockIdx.x;
    const int q8 = lane >> 3, rr = lane & 7;
    const int gid = lane >> 2, tig = lane & 3;
    const float scale2 = 0.17677669529663687f * 1.4426950408889634f;

    auto pf_chunk = [&](int chunk, FlashKV* KV) {
        int j0 = chunk * FCK;
        const __half* Kg = g_qkvf + (size_t)(b * L_ + j0) * QKVN_ + h * EH_ + QK_;
#pragma unroll
        for (int i = tid; i < 448; i += 224) {
            int row = i >> 2, seg = (i & 3) << 3;
            cpa16(smem_u32(&KV->Kh[row][seg]), Kg + (size_t)row * QKVN_ + seg);
        }
        const __half* Vg = Kg + QK_;
#pragma unroll
        for (int i = tid; i < 1792; i += 224) {
            int row = i >> 4, seg = (i & 15) << 3;
            cpa16(smem_u32(&KV->Vh[row][seg]), Vg + (size_t)row * QKVN_ + seg);
        }
    };

    {
        const __half* Qg = g_qkvf + (size_t)(b * L_ + qb * FQT) * QKVN_ + h * EH_;
#pragma unroll
        for (int i = tid; i < 448; i += 224) {
            int row = i >> 2, seg = (i & 3) << 3;
            cpa16(smem_u32(&SM.Qh[row][seg]), Qg + (size_t)row * QKVN_ + seg);
        }
    }
    pf_chunk(0, &SM.kv[0]); cpa_commit();
    pf_chunk(1, &SM.kv[1]); cpa_commit();

    cpa_wait<1>();
    __syncthreads();

    uint32_t qhf[2][4];
#pragma unroll
    for (int s = 0; s < 2; s++) {
        int arow = warp * 16 + (q8 & 1) * 8 + rr;
        int acol = s * 16 + (q8 >> 1) * 8;
        ldsm4(qhf[s][0], qhf[s][1], qhf[s][2], qhf[s][3], smem_u32(&SM.Qh[arow][acol]));
    }

    float out[16][4];
#pragma unroll
    for (int j = 0; j < 16; j++)
#pragma unroll
        for (int e = 0; e < 4; e++) out[j][e] = 0.f;
    float m0 = -1e30f, m1 = -1e30f, l0s = 0.f, l1s = 0.f;

    const int r0 = qb * FQT + warp * 16 + gid;
    const __nv_bfloat16* biasbase = g_biasbf + ((size_t)h * L_ + r0) * L_;

    for (int kc = 0; kc < 7; kc++) {
        int j0 = kc * FCK;
        if (kc > 0) {
            if (kc < 6) cpa_wait<1>(); else cpa_wait<0>();
            __syncthreads();
        }
        FlashKV& KV = SM.kv[kc & 1];

        // ---- S = Q K^T (single fp16 MMA) ----
        float sa[14][4];
#pragma unroll
        for (int t = 0; t < 14; t++)
#pragma unroll
            for (int e = 0; e < 4; e++) sa[t][e] = 0.f;
#pragma unroll
        for (int s = 0; s < 2; s++) {
#pragma unroll
            for (int tp = 0; tp < 7; tp++) {
                uint32_t bh[4];
                int brow = (tp * 2 + (q8 >> 1)) * 8 + rr;
                int bcol = s * 16 + (q8 & 1) * 8;
                ldsm4(bh[0], bh[1], bh[2], bh[3], smem_u32(&KV.Kh[brow][bcol]));
                mma16816h(sa[tp * 2 + 0], qhf[s], bh + 0);
                mma16816h(sa[tp * 2 + 1], qhf[s], bh + 2);
            }
        }

        // ---- (bias + scale)*log2e + row max (log2 domain) ----
        float ml0 = -1e30f, ml1 = -1e30f;
#pragma unroll
        for (int t = 0; t < 14; t++) {
            int col = j0 + t * 8 + tig * 2;
            float2 b0 = __bfloat1622float2(*(const __nv_bfloat162*)(biasbase + col));
            float2 b1 = __bfloat1622float2(*(const __nv_bfloat162*)(biasbase + (size_t)8 * L_ + col));
            sa[t][0] = fmaf(sa[t][0], scale2, b0.x);
            sa[t][1] = fmaf(sa[t][1], scale2, b0.y);
            sa[t][2] = fmaf(sa[t][2], scale2, b1.x);
            sa[t][3] = fmaf(sa[t][3], scale2, b1.y);
            ml0 = fmaxf(ml0, fmaxf(sa[t][0], sa[t][1]));
            ml1 = fmaxf(ml1, fmaxf(sa[t][2], sa[t][3]));
        }
        ml0 = fmaxf(ml0, __shfl_xor_sync(0xffffffffu, ml0, 1));
        ml0 = fmaxf(ml0, __shfl_xor_sync(0xffffffffu, ml0, 2));
        ml1 = fmaxf(ml1, __shfl_xor_sync(0xffffffffu, ml1, 1));
        ml1 = fmaxf(ml1, __shfl_xor_sync(0xffffffffu, ml1, 2));
        float mn0 = fmaxf(m0, ml0), mn1 = fmaxf(m1, ml1);
        float c0 = exp2f(m0 - mn0), c1 = exp2f(m1 - mn1);
        m0 = mn0; m1 = mn1;
#pragma unroll
        for (int j = 0; j < 16; j++) {
            out[j][0] *= c0; out[j][1] *= c0;
            out[j][2] *= c1; out[j][3] *= c1;
        }

        // ---- fused exp2 + PV (single fp16 MMA per tile) ----
        float rs0 = 0.f, rs1 = 0.f;
#pragma unroll
        for (int s2 = 0; s2 < 7; s2++) {
            uint32_t pah[4];
#pragma unroll
            for (int u = 0; u < 2; u++) {
                int t = s2 * 2 + u;
                float p0 = exp2f(sa[t][0] - mn0);
                float p1 = exp2f(sa[t][1] - mn0);
                float p2 = exp2f(sa[t][2] - mn1);
                float p3 = exp2f(sa[t][3] - mn1);
                rs0 += p0 + p1; rs1 += p2 + p3;
                __half2 h01 = __floats2half2_rn(p0, p1);
                __half2 h23 = __floats2half2_rn(p2, p3);
                pah[u * 2 + 0] = *(uint32_t*)&h01;
                pah[u * 2 + 1] = *(uint32_t*)&h23;
            }
#pragma unroll
            for (int jp = 0; jp < 8; jp++) {
                uint32_t vh[4];
                int vrow = s2 * 16 + (lane & 15);
                int vcol = (jp * 2 + (lane >> 4)) * 8;
                ldsm4t(vh[0], vh[1], vh[2], vh[3], smem_u32(&KV.Vh[vrow][vcol]));
                mma16816h(out[jp * 2 + 0], pah, vh + 0);
                mma16816h(out[jp * 2 + 1], pah, vh + 2);
            }
        }
        rs0 += __shfl_xor_sync(0xffffffffu, rs0, 1);
        rs0 += __shfl_xor_sync(0xffffffffu, rs0, 2);
        rs1 += __shfl_xor_sync(0xffffffffu, rs1, 1);
        rs1 += __shfl_xor_sync(0xffffffffu, rs1, 2);
        l0s = l0s * c0 + rs0;
        l1s = l1s * c1 + rs1;

        __syncthreads();
        if (kc + 2 <= 6) { pf_chunk(kc + 2, &SM.kv[kc & 1]); cpa_commit(); }
    }

    // ---- epilogue: normalize + fp16 write for proj GEMM ----
    float inv0 = 1.0f / l0s, inv1 = 1.0f / l1s;
    __half* of = g_aof + (size_t)(b * L_ + r0) * AON + h * VD_;
#pragma unroll
    for (int j = 0; j < 16; j++) {
        int col = j * 8 + tig * 2;
        {
            __half2 hh = __floats2half2_rn(out[j][0] * inv0, out[j][1] * inv0);
            *(uint32_t*)(of + col) = *(uint32_t*)&hh;
        }
        {
            __half2 hh = __floats2half2_rn(out[j][2] * inv1, out[j][3] * inv1);
            *(uint32_t*)(of + (size_t)8 * AON + col) = *(uint32_t*)&hh;
        }
    }
}

// ---------------- launch ---------------------------------------------------
extern "C" void kernel_launch(void* const* d_in, const int* in_sizes, int n_in,
                              void* d_out, int out_size) {
    const float* x         = (const float*)d_in[0];
    const float* Wqkv      = (const float*)d_in[1];
    const float* Wproj     = (const float*)d_in[2];
    const float* bproj     = (const float*)d_in[3];
    const float* ab_table  = (const float*)d_in[4];
    const int*   bias_idxs = (const int*)d_in[5];
    float* out = (float*)d_out;

    __half *pqkvf, *pxf, *pwqf, *paof, *pwph, *pwpl;
    cudaGetSymbolAddress((void**)&pxf, g_xf);
    cudaGetSymbolAddress((void**)&pwqf, g_wqf);
    cudaGetSymbolAddress((void**)&pwph, g_wph);
    cudaGetSymbolAddress((void**)&pwpl, g_wpl);
    cudaGetSymbolAddress((void**)&pqkvf, g_qkvf);
    cudaGetSymbolAddress((void**)&paof, g_aof);

    const int FSM = (int)sizeof(FlashSmemAll);   // 87808
    cudaFuncSetAttribute(flash_mma_kernel, cudaFuncAttributeMaxDynamicSharedMemorySize, FSM);
    const int GSMQ = 2 * 2 * 128 * GS * (int)sizeof(__half);   // 40960
    const int GSMP = 2 * 3 * 128 * GS * (int)sizeof(__half);   // 61440
    cudaFuncSetAttribute(gemm_qkv_f16, cudaFuncAttributeMaxDynamicSharedMemorySize, GSMQ);
    cudaFuncSetAttribute(gemm_proj_f16, cudaFuncAttributeMaxDynamicSharedMemorySize, GSMP);

    dim3 gbias(L_, H_);
    bias_fused_kernel<<<gbias, 256>>>(ab_table, bias_idxs);

    {
        int n0 = (B_ * L_ * D_) / 4;
        int n1 = (QKVN_ * D_) / 4;
        int n2 = (D_ * AON) / 4;
        int tot = n0 + n1 + n2;
        prep_kernel<<<(tot + 255) / 256, 256>>>(x, pxf, n0, Wqkv, pwqf, n1,
                                                Wproj, pwph, pwpl, n2);
    }

    dim3 gqkv(QKVN_ / 128, (B_ * L_) / 128);
    gemm_qkv_f16<<<gqkv, 256, GSMQ>>>(pxf, pwqf, pqkvf, B_ * L_, QKVN_, D_);

    dim3 gatt(L_ / FQT, H_, B_);
    flash_mma_kernel<<<gatt, 224, FSM>>>();

    dim3 gproj(D_ / 128, (B_ * L_) / 128);
    gemm_proj_f16<<<gproj, 256, GSMP>>>(paof, pwph, pwpl, bproj,
                                        out, B_ * L_, D_, AON);
}

// round 17
// speedup vs baseline: 1.5685x; 1.0294x over previous
#include <cuda_runtime.h>
#include <cuda_bf16.h>
#include <cuda_fp16.h>
#include <math.h>
#include <cstdint>

#define B_     16
#define L_     784
#define D_     384
#define H_     8
#define QK_    32
#define VD_    128
#define EH_    192          // per-head qkv width
#define QKVN_  1536
#define RESI_  625

#define FQT 112             // q rows per CTA (784 = 7*112)
#define FCK 112             // keys per chunk
#define VSTR 136            // V smem stride in fp16 (conflict-free trans ldsm)
#define KSTR 40             // K/Q smem stride in fp16
#define AON  (H_ * VD_)     // 1024
#define GS   40             // GEMM smem stride

// ---------------- scratch (static device globals; no runtime alloc) --------
__device__ __half        g_qkvf[(size_t)B_ * L_ * QKVN_];   // fp16 qkv for flash
__device__ __half        g_aof[(size_t)B_ * L_ * AON];      // fp16 attention out
__device__ __nv_bfloat16 g_biasbf[(size_t)H_ * L_ * L_];    // bias * log2(e)
__device__ __half        g_xf[(size_t)B_ * L_ * D_];
__device__ __half        g_wqf[QKVN_ * D_];
__device__ __half        g_wph[D_ * AON];                   // Wproj hi (fp16)
__device__ __half        g_wpl[D_ * AON];                   // Wproj lo (fp16 residual)

__device__ __forceinline__ uint32_t smem_u32(const void* p) {
    uint32_t a;
    asm("{ .reg .u64 t; cvta.to.shared.u64 t, %1; cvt.u32.u64 %0, t; }" : "=r"(a) : "l"(p));
    return a;
}
__device__ __forceinline__ void cpa16(uint32_t s, const void* g) {
    asm volatile("cp.async.cg.shared.global [%0], [%1], 16;" :: "r"(s), "l"(g));
}
__device__ __forceinline__ void cpa_commit() {
    asm volatile("cp.async.commit_group;" ::: "memory");
}
template <int N> __device__ __forceinline__ void cpa_wait() {
    asm volatile("cp.async.wait_group %0;" :: "n"(N) : "memory");
}
__device__ __forceinline__ uint32_t h2ex2(uint32_t x) {
    uint32_t r; asm("ex2.approx.f16x2 %0, %1;" : "=r"(r) : "r"(x)); return r;
}

// ---------------- inline bicubic weights (RESI_/L_ resample) ---------------
__device__ __forceinline__ void interp4(int o, float* w, int* id) {
    const float a = -0.75f;
    float scale = (float)RESI_ / (float)L_;
    float src = ((float)o + 0.5f) * scale - 0.5f;
    float f = floorf(src);
    float t = src - f;
    float xs[4] = { t + 1.0f, t, 1.0f - t, 2.0f - t };
#pragma unroll
    for (int i = 0; i < 4; i++) {
        float ax = fabsf(xs[i]);
        float w1 = ((a + 2.0f) * ax - (a + 3.0f)) * ax * ax + 1.0f;
        float w2 = a * (((ax - 5.0f) * ax + 8.0f) * ax - 4.0f);
        w[i] = (ax <= 1.0f) ? w1 : ((ax < 2.0f) ? w2 : 0.0f);
        int v = (int)f - 1 + i;
        id[i] = v < 0 ? 0 : (v > RESI_ - 1 ? RESI_ - 1 : v);
    }
}

// ---------------- K1: merged bias build + prep (concurrent) -----------------
// blocks [0, 6272): bias for (o = bid%784, h = bid/784)
// blocks [6272, ..): prep element groups
#define BIAS_BLOCKS (L_ * H_)
__global__ __launch_bounds__(256) void bias_prep_kernel(
    const float* __restrict__ ab_table, const int* __restrict__ bias_idxs,
    const float* __restrict__ s0, __half* __restrict__ d0, int n0,
    const float* __restrict__ s1, __half* __restrict__ d1, int n1,
    const float* __restrict__ s2, __half* __restrict__ h2,
    __half* __restrict__ l2p, int n2)
{
    __shared__ float tr[RESI_];
    int bid = blockIdx.x;
    if (bid < BIAS_BLOCKS) {
        const float LOG2E = 1.4426950408889634f;
        int o = bid % L_, h = bid / L_;
        float wo[4]; int io[4];
        interp4(o, wo, io);
        const float* __restrict__ tab = ab_table + (size_t)h * RESI_;
        for (int j = threadIdx.x; j < RESI_; j += 256) {
            float s = 0.f;
#pragma unroll
            for (int a = 0; a < 4; a++) {
                int idx = __ldg(bias_idxs + (size_t)io[a] * RESI_ + j);
                s = fmaf(wo[a], __ldg(tab + idx), s);
            }
            tr[j] = s;
        }
        __syncthreads();
        __nv_bfloat16* dst = g_biasbf + ((size_t)h * L_ + o) * L_;
        for (int p = threadIdx.x; p < L_; p += 256) {
            float wp[4]; int ip[4];
            interp4(p, wp, ip);
            float s = 0.f;
#pragma unroll
            for (int bb = 0; bb < 4; bb++)
                s = fmaf(wp[bb], tr[ip[bb]], s);
            dst[p] = __float2bfloat16(s * LOG2E);
        }
    } else {
        int i = (bid - BIAS_BLOCKS) * 256 + threadIdx.x;
        if (i < n0 + n1) {
            const float* src = (i < n0) ? s0 : s1;
            __half* dst = (i < n0) ? d0 : d1;
            if (i >= n0) i -= n0;
            float4 v = *(const float4*)(src + (size_t)i * 4);
            __half2 a = __floats2half2_rn(v.x, v.y);
            __half2 b = __floats2half2_rn(v.z, v.w);
            *(uint2*)(dst + (size_t)i * 4) = make_uint2(*(uint32_t*)&a, *(uint32_t*)&b);
        } else if (i < n0 + n1 + n2) {
            i -= n0 + n1;
            float4 v = *(const float4*)(s2 + (size_t)i * 4);
            __half2 h01 = __floats2half2_rn(v.x, v.y);
            __half2 h23 = __floats2half2_rn(v.z, v.w);
            float l0 = v.x - __half2float(h01.x), l1 = v.y - __half2float(h01.y);
            float l2 = v.z - __half2float(h23.x), l3 = v.w - __half2float(h23.y);
            __half2 q01 = __floats2half2_rn(l0, l1);
            __half2 q23 = __floats2half2_rn(l2, l3);
            *(uint2*)(h2 + (size_t)i * 4) = make_uint2(*(uint32_t*)&h01, *(uint32_t*)&h23);
            *(uint2*)(l2p + (size_t)i * 4) = make_uint2(*(uint32_t*)&q01, *(uint32_t*)&q23);
        }
    }
}

// ---------------- mma.sync helpers -----------------------------------------
__device__ __forceinline__ void ldsm4(uint32_t& r0, uint32_t& r1, uint32_t& r2, uint32_t& r3,
                                      uint32_t addr) {
    asm volatile("ldmatrix.sync.aligned.m8n8.x4.shared.b16 {%0,%1,%2,%3}, [%4];"
                 : "=r"(r0), "=r"(r1), "=r"(r2), "=r"(r3) : "r"(addr));
}
__device__ __forceinline__ void ldsm4t(uint32_t& r0, uint32_t& r1, uint32_t& r2, uint32_t& r3,
                                       uint32_t addr) {
    asm volatile("ldmatrix.sync.aligned.m8n8.x4.trans.shared.b16 {%0,%1,%2,%3}, [%4];"
                 : "=r"(r0), "=r"(r1), "=r"(r2), "=r"(r3) : "r"(addr));
}
__device__ __forceinline__ void mma16816h(float* d, const uint32_t* a, const uint32_t* b) {
    asm volatile("mma.sync.aligned.m16n8k16.row.col.f32.f16.f16.f32 "
                 "{%0,%1,%2,%3}, {%4,%5,%6,%7}, {%8,%9}, {%0,%1,%2,%3};"
                 : "+f"(d[0]), "+f"(d[1]), "+f"(d[2]), "+f"(d[3])
                 : "r"(a[0]), "r"(a[1]), "r"(a[2]), "r"(a[3]), "r"(b[0]), "r"(b[1]));
}

// ---------------- K3: QKV GEMM, fp16 single-MMA, 3-stage pipeline -----------
__global__ __launch_bounds__(256) void gemm_qkv_f16(
    const __half* __restrict__ Ag, const __half* __restrict__ Wg,
    __half* __restrict__ C, int M, int N, int K)
{
    extern __shared__ __align__(16) __half smh[];
    const int TS = 128 * GS;

    const int tid = threadIdx.x;
    const int wid = tid >> 5;
    const int lane = tid & 31;
    const int wm = wid >> 2;
    const int wn = wid & 3;
    const int bm = blockIdx.y * 128;
    const int bn = blockIdx.x * 128;
    const int q = lane >> 3;
    const int rr = lane & 7;

    float acc[4][4][4];
#pragma unroll
    for (int i = 0; i < 4; i++)
#pragma unroll
        for (int j = 0; j < 4; j++)
#pragma unroll
            for (int e = 0; e < 4; e++) acc[i][j][e] = 0.f;

    const int nch = K >> 5;

    auto prefetch = [&](int chunk, int stage) {
        int k0 = chunk << 5;
        __half* T = smh + stage * 2 * TS;
        const __half* gA = Ag + (size_t)bm * K + k0;
        const __half* gW = Wg + (size_t)bn * K + k0;
#pragma unroll
        for (int i = tid; i < 512; i += 256) {
            int row = i >> 2, seg = (i & 3) << 3;
            cpa16(smem_u32(T + row * GS + seg), gA + (size_t)row * K + seg);
            cpa16(smem_u32(T + TS + row * GS + seg), gW + (size_t)row * K + seg);
        }
    };

    prefetch(0, 0); cpa_commit();
    prefetch(1, 1); cpa_commit();
    prefetch(2, 2); cpa_commit();

    for (int i = 0; i < nch; i++) {
        if (i + 2 < nch) cpa_wait<2>();
        else if (i + 1 < nch) cpa_wait<1>();
        else cpa_wait<0>();
        __syncthreads();
        int st = i % 3;
        const __half* TA = smh + st * 2 * TS;
        const __half* TB = TA + TS;

#pragma unroll
        for (int ks = 0; ks < 2; ks++) {
            int kc = ks * 16;
            uint32_t ah[4][4];
#pragma unroll
            for (int ii2 = 0; ii2 < 4; ii2++) {
                int arow = wm * 64 + ii2 * 16 + (q & 1) * 8 + rr;
                int acol = kc + (q >> 1) * 8;
                ldsm4(ah[ii2][0], ah[ii2][1], ah[ii2][2], ah[ii2][3],
                      smem_u32(TA + arow * GS + acol));
            }
            uint32_t bh[4][2];
#pragma unroll
            for (int jp = 0; jp < 2; jp++) {
                int brow = wn * 32 + (jp * 2 + (q >> 1)) * 8 + rr;
                int bcol = kc + (q & 1) * 8;
                ldsm4(bh[jp * 2][0], bh[jp * 2][1], bh[jp * 2 + 1][0], bh[jp * 2 + 1][1],
                      smem_u32(TB + brow * GS + bcol));
            }
#pragma unroll
            for (int ii2 = 0; ii2 < 4; ii2++)
#pragma unroll
                for (int j = 0; j < 4; j++)
                    mma16816h(acc[ii2][j], ah[ii2], bh[j]);
        }
        __syncthreads();
        if (i + 3 < nch) { prefetch(i + 3, i % 3); cpa_commit(); }
    }

    const int gid = lane >> 2;
    const int tig = lane & 3;
#pragma unroll
    for (int i = 0; i < 4; i++) {
#pragma unroll
        for (int j = 0; j < 4; j++) {
            int row0 = bm + wm * 64 + i * 16 + gid;
            int col = bn + wn * 32 + j * 8 + tig * 2;
#pragma unroll
            for (int u = 0; u < 2; u++) {
                __half2 hh = __floats2half2_rn(acc[i][j][u * 2 + 0], acc[i][j][u * 2 + 1]);
                *(uint32_t*)(C + (size_t)(row0 + u * 8) * N + col) = *(uint32_t*)&hh;
            }
        }
    }
}

// ---------------- K5: proj GEMM: A fp16 x (Wh + Wl), 3-stage pipeline -------
__global__ __launch_bounds__(256) void gemm_proj_f16(
    const __half* __restrict__ Ag,
    const __half* __restrict__ Whg, const __half* __restrict__ Wlg,
    const float* __restrict__ bias, float* __restrict__ Cf,
    int M, int N, int K)
{
    extern __shared__ __align__(16) __half smh[];
    const int TS = 128 * GS;

    const int tid = threadIdx.x;
    const int wid = tid >> 5;
    const int lane = tid & 31;
    const int wm = wid >> 2;
    const int wn = wid & 3;
    const int bm = blockIdx.y * 128;
    const int bn = blockIdx.x * 128;
    const int q = lane >> 3;
    const int rr = lane & 7;

    float acc[4][4][4];
#pragma unroll
    for (int i = 0; i < 4; i++)
#pragma unroll
        for (int j = 0; j < 4; j++)
#pragma unroll
            for (int e = 0; e < 4; e++) acc[i][j][e] = 0.f;

    const int nch = K >> 5;

    auto prefetch = [&](int chunk, int stage) {
        int k0 = chunk << 5;
        __half* T = smh + stage * 3 * TS;
        const __half* gA = Ag + (size_t)bm * K + k0;
        const __half* gH = Whg + (size_t)bn * K + k0;
        const __half* gL = Wlg + (size_t)bn * K + k0;
#pragma unroll
        for (int i = tid; i < 512; i += 256) {
            int row = i >> 2, seg = (i & 3) << 3;
            cpa16(smem_u32(T + row * GS + seg), gA + (size_t)row * K + seg);
            cpa16(smem_u32(T + TS + row * GS + seg), gH + (size_t)row * K + seg);
            cpa16(smem_u32(T + 2 * TS + row * GS + seg), gL + (size_t)row * K + seg);
        }
    };

    prefetch(0, 0); cpa_commit();
    prefetch(1, 1); cpa_commit();
    prefetch(2, 2); cpa_commit();

    for (int i = 0; i < nch; i++) {
        if (i + 2 < nch) cpa_wait<2>();
        else if (i + 1 < nch) cpa_wait<1>();
        else cpa_wait<0>();
        __syncthreads();
        int st = i % 3;
        const __half* TA = smh + st * 3 * TS;
        const __half* TH = TA + TS;
        const __half* TL = TA + 2 * TS;

#pragma unroll
        for (int ks = 0; ks < 2; ks++) {
            int kc = ks * 16;
            uint32_t ah[4][4];
#pragma unroll
            for (int ii2 = 0; ii2 < 4; ii2++) {
                int arow = wm * 64 + ii2 * 16 + (q & 1) * 8 + rr;
                int acol = kc + (q >> 1) * 8;
                ldsm4(ah[ii2][0], ah[ii2][1], ah[ii2][2], ah[ii2][3],
                      smem_u32(TA + arow * GS + acol));
            }
            uint32_t bh[4][2], bl[4][2];
#pragma unroll
            for (int jp = 0; jp < 2; jp++) {
                int brow = wn * 32 + (jp * 2 + (q >> 1)) * 8 + rr;
                int bcol = kc + (q & 1) * 8;
                ldsm4(bh[jp * 2][0], bh[jp * 2][1], bh[jp * 2 + 1][0], bh[jp * 2 + 1][1],
                      smem_u32(TH + brow * GS + bcol));
                ldsm4(bl[jp * 2][0], bl[jp * 2][1], bl[jp * 2 + 1][0], bl[jp * 2 + 1][1],
                      smem_u32(TL + brow * GS + bcol));
            }
#pragma unroll
            for (int ii2 = 0; ii2 < 4; ii2++)
#pragma unroll
                for (int j = 0; j < 4; j++) {
                    mma16816h(acc[ii2][j], ah[ii2], bh[j]);
                    mma16816h(acc[ii2][j], ah[ii2], bl[j]);
                }
        }
        __syncthreads();
        if (i + 3 < nch) { prefetch(i + 3, i % 3); cpa_commit(); }
    }

    const int gid = lane >> 2;
    const int tig = lane & 3;
#pragma unroll
    for (int i = 0; i < 4; i++) {
#pragma unroll
        for (int j = 0; j < 4; j++) {
            int row0 = bm + wm * 64 + i * 16 + gid;
            int col = bn + wn * 32 + j * 8 + tig * 2;
            float2 v0 = make_float2(acc[i][j][0] + bias[col], acc[i][j][1] + bias[col + 1]);
            float2 v1 = make_float2(acc[i][j][2] + bias[col], acc[i][j][3] + bias[col + 1]);
            *(float2*)(Cf + (size_t)row0 * N + col) = v0;
            *(float2*)(Cf + (size_t)(row0 + 8) * N + col) = v1;
        }
    }
}

// ---------------- K4: fp16 flash attention, double-buffered, 2 CTAs/SM ------
struct FlashKV {
    __half Kh[FQT][KSTR];
    __half Vh[FCK][VSTR];
};
struct FlashSmemAll {
    __half Qh[FQT][KSTR];
    FlashKV kv[2];
};

__global__ __launch_bounds__(224, 2) void flash_mma_kernel() {
    extern __shared__ __align__(16) char smraw[];
    FlashSmemAll& SM = *reinterpret_cast<FlashSmemAll*>(smraw);
    const int tid = threadIdx.x;
    const int warp = tid >> 5, lane = tid & 31;
    const int b = blockIdx.z, h = blockIdx.y, qb = blockIdx.x;
    const int q8 = lane >> 3, rr = lane & 7;
    const int gid = lane >> 2, tig = lane & 3;
    const float scale2 = 0.17677669529663687f * 1.4426950408889634f;

    auto pf_chunk = [&](int chunk, FlashKV* KV) {
        int j0 = chunk * FCK;
        const __half* Kg = g_qkvf + (size_t)(b * L_ + j0) * QKVN_ + h * EH_ + QK_;
#pragma unroll
        for (int i = tid; i < 448; i += 224) {
            int row = i >> 2, seg = (i & 3) << 3;
            cpa16(smem_u32(&KV->Kh[row][seg]), Kg + (size_t)row * QKVN_ + seg);
        }
        const __half* Vg = Kg + QK_;
#pragma unroll
        for (int i = tid; i < 1792; i += 224) {
            int row = i >> 4, seg = (i & 15) << 3;
            cpa16(smem_u32(&KV->Vh[row][seg]), Vg + (size_t)row * QKVN_ + seg);
        }
    };

    {
        const __half* Qg = g_qkvf + (size_t)(b * L_ + qb * FQT) * QKVN_ + h * EH_;
#pragma unroll
        for (int i = tid; i < 448; i += 224) {
            int row = i >> 2, seg = (i & 3) << 3;
            cpa16(smem_u32(&SM.Qh[row][seg]), Qg + (size_t)row * QKVN_ + seg);
        }
    }
    pf_chunk(0, &SM.kv[0]); cpa_commit();
    pf_chunk(1, &SM.kv[1]); cpa_commit();

    cpa_wait<1>();
    __syncthreads();

    uint32_t qhf[2][4];
#pragma unroll
    for (int s = 0; s < 2; s++) {
        int arow = warp * 16 + (q8 & 1) * 8 + rr;
        int acol = s * 16 + (q8 >> 1) * 8;
        ldsm4(qhf[s][0], qhf[s][1], qhf[s][2], qhf[s][3], smem_u32(&SM.Qh[arow][acol]));
    }

    float out[16][4];
#pragma unroll
    for (int j = 0; j < 16; j++)
#pragma unroll
        for (int e = 0; e < 4; e++) out[j][e] = 0.f;
    float m0 = -1e30f, m1 = -1e30f, l0s = 0.f, l1s = 0.f;

    const int r0 = qb * FQT + warp * 16 + gid;
    const __nv_bfloat16* biasbase = g_biasbf + ((size_t)h * L_ + r0) * L_;

    for (int kc = 0; kc < 7; kc++) {
        int j0 = kc * FCK;
        if (kc > 0) {
            if (kc < 6) cpa_wait<1>(); else cpa_wait<0>();
            __syncthreads();
        }
        FlashKV& KV = SM.kv[kc & 1];

        // ---- S = Q K^T (single fp16 MMA) ----
        float sa[14][4];
#pragma unroll
        for (int t = 0; t < 14; t++)
#pragma unroll
            for (int e = 0; e < 4; e++) sa[t][e] = 0.f;
#pragma unroll
        for (int s = 0; s < 2; s++) {
#pragma unroll
            for (int tp = 0; tp < 7; tp++) {
                uint32_t bh[4];
                int brow = (tp * 2 + (q8 >> 1)) * 8 + rr;
                int bcol = s * 16 + (q8 & 1) * 8;
                ldsm4(bh[0], bh[1], bh[2], bh[3], smem_u32(&KV.Kh[brow][bcol]));
                mma16816h(sa[tp * 2 + 0], qhf[s], bh + 0);
                mma16816h(sa[tp * 2 + 1], qhf[s], bh + 2);
            }
        }

        // ---- (bias + scale)*log2e + row max (log2 domain) ----
        float ml0 = -1e30f, ml1 = -1e30f;
#pragma unroll
        for (int t = 0; t < 14; t++) {
            int col = j0 + t * 8 + tig * 2;
            float2 b0 = __bfloat1622float2(*(const __nv_bfloat162*)(biasbase + col));
            float2 b1 = __bfloat1622float2(*(const __nv_bfloat162*)(biasbase + (size_t)8 * L_ + col));
            sa[t][0] = fmaf(sa[t][0], scale2, b0.x);
            sa[t][1] = fmaf(sa[t][1], scale2, b0.y);
            sa[t][2] = fmaf(sa[t][2], scale2, b1.x);
            sa[t][3] = fmaf(sa[t][3], scale2, b1.y);
            ml0 = fmaxf(ml0, fmaxf(sa[t][0], sa[t][1]));
            ml1 = fmaxf(ml1, fmaxf(sa[t][2], sa[t][3]));
        }
        ml0 = fmaxf(ml0, __shfl_xor_sync(0xffffffffu, ml0, 1));
        ml0 = fmaxf(ml0, __shfl_xor_sync(0xffffffffu, ml0, 2));
        ml1 = fmaxf(ml1, __shfl_xor_sync(0xffffffffu, ml1, 1));
        ml1 = fmaxf(ml1, __shfl_xor_sync(0xffffffffu, ml1, 2));
        float mn0 = fmaxf(m0, ml0), mn1 = fmaxf(m1, ml1);
        float c0 = exp2f(m0 - mn0), c1 = exp2f(m1 - mn1);
        m0 = mn0; m1 = mn1;
#pragma unroll
        for (int j = 0; j < 16; j++) {
            out[j][0] *= c0; out[j][1] *= c0;
            out[j][2] *= c1; out[j][3] *= c1;
        }

        // ---- fused exp2 (f16x2 MUFU) + PV ----
        float rs0 = 0.f, rs1 = 0.f;
#pragma unroll
        for (int s2 = 0; s2 < 7; s2++) {
            uint32_t pah[4];
#pragma unroll
            for (int u = 0; u < 2; u++) {
                int t = s2 * 2 + u;
                __half2 e01 = __floats2half2_rn(sa[t][0] - mn0, sa[t][1] - mn0);
                __half2 e23 = __floats2half2_rn(sa[t][2] - mn1, sa[t][3] - mn1);
                uint32_t p01 = h2ex2(*(uint32_t*)&e01);
                uint32_t p23 = h2ex2(*(uint32_t*)&e23);
                pah[u * 2 + 0] = p01;
                pah[u * 2 + 1] = p23;
                float2 f01 = __half22float2(*(__half2*)&p01);
                float2 f23 = __half22float2(*(__half2*)&p23);
                rs0 += f01.x + f01.y;
                rs1 += f23.x + f23.y;
            }
#pragma unroll
            for (int jp = 0; jp < 8; jp++) {
                uint32_t vh[4];
                int vrow = s2 * 16 + (lane & 15);
                int vcol = (jp * 2 + (lane >> 4)) * 8;
                ldsm4t(vh[0], vh[1], vh[2], vh[3], smem_u32(&KV.Vh[vrow][vcol]));
                mma16816h(out[jp * 2 + 0], pah, vh + 0);
                mma16816h(out[jp * 2 + 1], pah, vh + 2);
            }
        }
        rs0 += __shfl_xor_sync(0xffffffffu, rs0, 1);
        rs0 += __shfl_xor_sync(0xffffffffu, rs0, 2);
        rs1 += __shfl_xor_sync(0xffffffffu, rs1, 1);
        rs1 += __shfl_xor_sync(0xffffffffu, rs1, 2);
        l0s = l0s * c0 + rs0;
        l1s = l1s * c1 + rs1;

        __syncthreads();
        if (kc + 2 <= 6) { pf_chunk(kc + 2, &SM.kv[kc & 1]); cpa_commit(); }
    }

    // ---- epilogue: normalize + fp16 write for proj GEMM ----
    float inv0 = 1.0f / l0s, inv1 = 1.0f / l1s;
    __half* of = g_aof + (size_t)(b * L_ + r0) * AON + h * VD_;
#pragma unroll
    for (int j = 0; j < 16; j++) {
        int col = j * 8 + tig * 2;
        {
            __half2 hh = __floats2half2_rn(out[j][0] * inv0, out[j][1] * inv0);
            *(uint32_t*)(of + col) = *(uint32_t*)&hh;
        }
        {
            __half2 hh = __floats2half2_rn(out[j][2] * inv1, out[j][3] * inv1);
            *(uint32_t*)(of + (size_t)8 * AON + col) = *(uint32_t*)&hh;
        }
    }
}

// ---------------- launch ---------------------------------------------------
extern "C" void kernel_launch(void* const* d_in, const int* in_sizes, int n_in,
                              void* d_out, int out_size) {
    const float* x         = (const float*)d_in[0];
    const float* Wqkv      = (const float*)d_in[1];
    const float* Wproj     = (const float*)d_in[2];
    const float* bproj     = (const float*)d_in[3];
    const float* ab_table  = (const float*)d_in[4];
    const int*   bias_idxs = (const int*)d_in[5];
    float* out = (float*)d_out;

    __half *pqkvf, *pxf, *pwqf, *paof, *pwph, *pwpl;
    cudaGetSymbolAddress((void**)&pxf, g_xf);
    cudaGetSymbolAddress((void**)&pwqf, g_wqf);
    cudaGetSymbolAddress((void**)&pwph, g_wph);
    cudaGetSymbolAddress((void**)&pwpl, g_wpl);
    cudaGetSymbolAddress((void**)&pqkvf, g_qkvf);
    cudaGetSymbolAddress((void**)&paof, g_aof);

    const int FSM = (int)sizeof(FlashSmemAll);   // 87808
    cudaFuncSetAttribute(flash_mma_kernel, cudaFuncAttributeMaxDynamicSharedMemorySize, FSM);
    const int GSMQ = 3 * 2 * 128 * GS * (int)sizeof(__half);   // 61440
    const int GSMP = 3 * 3 * 128 * GS * (int)sizeof(__half);   // 92160
    cudaFuncSetAttribute(gemm_qkv_f16, cudaFuncAttributeMaxDynamicSharedMemorySize, GSMQ);
    cudaFuncSetAttribute(gemm_proj_f16, cudaFuncAttributeMaxDynamicSharedMemorySize, GSMP);

    // merged bias + prep (concurrent within one grid)
    {
        int n0 = (B_ * L_ * D_) / 4;
        int n1 = (QKVN_ * D_) / 4;
        int n2 = (D_ * AON) / 4;
        int prep_blocks = (n0 + n1 + n2 + 255) / 256;
        bias_prep_kernel<<<BIAS_BLOCKS + prep_blocks, 256>>>(
            ab_table, bias_idxs, x, pxf, n0, Wqkv, pwqf, n1,
            Wproj, pwph, pwpl, n2);
    }

    dim3 gqkv(QKVN_ / 128, (B_ * L_) / 128);
    gemm_qkv_f16<<<gqkv, 256, GSMQ>>>(pxf, pwqf, pqkvf, B_ * L_, QKVN_, D_);

    dim3 gatt(L_ / FQT, H_, B_);
    flash_mma_kernel<<<gatt, 224, FSM>>>();

    dim3 gproj(D_ / 128, (B_ * L_) / 128);
    gemm_proj_f16<<<gproj, 256, GSMP>>>(paof, pwph, pwpl, bproj,
                                        out, B_ * L_, D_, AON);
}